// round 5
// baseline (speedup 1.0000x reference)
#include <cuda_runtime.h>
#include <cuda_fp16.h>

#define TT 512
#define BB 512
#define DD 16
#define HH 64
#define G3 192
#define PT 32          // timesteps per precompute CTA
#define BK 8           // timesteps per staged block in rec kernel
#define NBK (TT / BK)
#define RR 2           // batch rows per rec CTA (share weight registers)

typedef unsigned long long ull;

__device__ __forceinline__ ull fma2(ull a, ull b, ull c) {
    ull d;
    asm("fma.rn.f32x2 %0, %1, %2, %3;" : "=l"(d) : "l"(a), "l"(b), "l"(c));
    return d;
}
__device__ __forceinline__ ull addf2(ull a, ull b) {
    ull d;
    asm("add.rn.f32x2 %0, %1, %2;" : "=l"(d) : "l"(a), "l"(b));
    return d;
}
__device__ __forceinline__ float hadd2(ull a) {
    return __uint_as_float((unsigned)a) + __uint_as_float((unsigned)(a >> 32));
}
__device__ __forceinline__ float tanha(float x) {
    float y;
    asm("tanh.approx.f32 %0, %1;" : "=f"(y) : "f"(x));
    return y;
}
__device__ __forceinline__ float siga(float x) {
    return fmaf(0.5f, tanha(0.5f * x), 0.5f);
}
__device__ __forceinline__ void cpa16(unsigned smem, const void* gmem) {
    asm volatile("cp.async.ca.shared.global [%0], [%1], 16;\n"
                 :: "r"(smem), "l"(gmem));
}
__device__ __forceinline__ void cpa_commit() {
    asm volatile("cp.async.commit_group;\n" ::: "memory");
}
__device__ __forceinline__ void cpa_wait1() {
    asm volatile("cp.async.wait_group 1;\n" ::: "memory");
}

// scratch: precomputed input projections xg[b][t][g] (includes b_ih), fp16
__device__ __half g_xg[(size_t)BB * TT * G3];

// ---------------------------------------------------------------------------
// Kernel 1: xg = x @ w_ih^T + b_ih for all (b,t), stored fp16.
// ---------------------------------------------------------------------------
__global__ __launch_bounds__(G3)
void xg_kernel(const float* __restrict__ x,
               const float* __restrict__ w_ih,
               const float* __restrict__ b_ih)
{
    __shared__ __align__(16) float xs[PT][DD];
    const int g  = threadIdx.x;
    const int b  = blockIdx.y;
    const int t0 = blockIdx.x * PT;

    ulonglong2 wv[DD / 4];
    {
        const ulonglong2* p = (const ulonglong2*)(w_ih + g * DD);
        #pragma unroll
        for (int j = 0; j < DD / 4; j++) wv[j] = p[j];
    }
    const float bias = b_ih[g];

    for (int i = g; i < PT * DD / 4; i += G3)
        ((float4*)&xs[0][0])[i] =
            ((const float4*)(x + ((size_t)b * TT + t0) * DD))[i];
    __syncthreads();

    #pragma unroll 8
    for (int tt = 0; tt < PT; tt++) {
        const ulonglong2* xp = (const ulonglong2*)xs[tt];
        ull a0 = 0ull, a1 = 0ull;
        #pragma unroll
        for (int j = 0; j < DD / 4; j++) {
            ulonglong2 xv = xp[j];
            a0 = fma2(wv[j].x, xv.x, a0);
            a1 = fma2(wv[j].y, xv.y, a1);
        }
        g_xg[((size_t)b * TT + t0 + tt) * G3 + g] =
            __float2half_rn(hadd2(a0) + hadd2(a1) + bias);
    }
}

// ---------------------------------------------------------------------------
// Kernel 2: forward recurrence. CTA = 64 threads = RR=2 batch rows (weights
// shared in registers across rows). Warp s: k-half [32s,32s+32), finalizes
// units [32s,32s+32) for BOTH rows. One CTA barrier per step. xg staged via
// cp.async in 8-step blocks (fp16). Partials exchanged as packed f32x2.
// ---------------------------------------------------------------------------
__global__ __launch_bounds__(64, 4)
void gru_rec_kernel(const float* __restrict__ w_hh,
                    const float* __restrict__ b_hh,
                    const float* __restrict__ x,
                    const float* __restrict__ w_ih_b,
                    const float* __restrict__ b_ih_b,
                    const float* __restrict__ b_hh_b,
                    const float* __restrict__ fc_w,
                    const float* __restrict__ fc_b,
                    float* __restrict__ out)
{
    __shared__ __align__(16) float h_sh[RR][HH];
    __shared__ ull part_sh[2][RR][2][3][32];   // [parity][row][src warp][gate][lane]
    __shared__ __align__(16) __half xg_sh[2][RR][BK * G3];  // [buf][row][...]
    __shared__ float red_sh[RR][HH];

    const int tid = threadIdx.x;
    const int s   = tid >> 5;
    const int l   = tid & 31;
    const int b0  = blockIdx.x * RR;
    const int u   = 32 * s + l;

    // weights: rows (r,z,n) of unit l and unit 32+l, k-range [32s, 32s+32)
    // i: 0:r(l) 1:z(l) 2:n(l) 3:r(32+l) 4:z(32+l) 5:n(32+l)
    ulonglong2 w[6][8];
    {
        const int rows[6] = { l, HH + l, 2 * HH + l,
                              32 + l, HH + 32 + l, 2 * HH + 32 + l };
        #pragma unroll
        for (int i = 0; i < 6; i++) {
            const ulonglong2* p = (const ulonglong2*)(w_hh + rows[i] * HH + 32 * s);
            #pragma unroll
            for (int j = 0; j < 8; j++) w[i][j] = p[j];
        }
    }
    const float bhr = b_hh[u];
    const float bhz = b_hh[HH + u];
    const float bhn = b_hh[2 * HH + u];

    const char* xg_g0 = (const char*)(g_xg + (size_t)(b0 + 0) * TT * G3);
    const char* xg_g1 = (const char*)(g_xg + (size_t)(b0 + 1) * TT * G3);
    const unsigned xg_sb = (unsigned)__cvta_generic_to_shared(&xg_sh[0][0][0]);
    // per (buf,row): 3072 bytes = 192 x 16B chunks; 3 chunks/thread/row

    float hold0 = 0.f, hold1 = 0.f;
    h_sh[0][u] = 0.f;
    h_sh[1][u] = 0.f;

    // prologue: stage block 0 into buffer 0 (both rows)
    {
        #pragma unroll
        for (int c = 0; c < 3; c++) {
            cpa16(xg_sb + (tid + 64 * c) * 16,             xg_g0 + (tid + 64 * c) * 16);
            cpa16(xg_sb + 3072 + (tid + 64 * c) * 16,      xg_g1 + (tid + 64 * c) * 16);
        }
        cpa_commit();
    }
    __syncthreads();

    const int eo = s ? 0 : 3;   // gate-rows exported to the other warp
    const int ko = s ? 3 : 0;   // gate-rows kept

    int p = 0;
    for (int blk = 0; blk < NBK; ++blk) {
        if (blk + 1 < NBK) {
            unsigned dst = xg_sb + ((blk & 1) ? 0u : 6144u);   // buffer (blk+1)&1
            const char* s0 = xg_g0 + (size_t)(blk + 1) * 3072;
            const char* s1 = xg_g1 + (size_t)(blk + 1) * 3072;
            #pragma unroll
            for (int c = 0; c < 3; c++) {
                cpa16(dst + (tid + 64 * c) * 16,        s0 + (tid + 64 * c) * 16);
                cpa16(dst + 3072 + (tid + 64 * c) * 16, s1 + (tid + 64 * c) * 16);
            }
        }
        cpa_commit();
        cpa_wait1();
        __syncthreads();

        const __half* xb0 = &xg_sh[blk & 1][0][0];
        const __half* xb1 = &xg_sh[blk & 1][1][0];

        #pragma unroll
        for (int tt = 0; tt < BK; ++tt) {
            // xg for this step, both rows (SMEM fp16)
            float c00 = __half2float(xb0[tt * G3 + u]);
            float c01 = __half2float(xb0[tt * G3 + HH + u]);
            float c02 = __half2float(xb0[tt * G3 + 2 * HH + u]);
            float c10 = __half2float(xb1[tt * G3 + u]);
            float c11 = __half2float(xb1[tt * G3 + HH + u]);
            float c12 = __half2float(xb1[tt * G3 + 2 * HH + u]);

            // partial dots over this warp's k-half, both rows (shared weights)
            const ulonglong2* hp0 = (const ulonglong2*)&h_sh[0][32 * s];
            const ulonglong2* hp1 = (const ulonglong2*)&h_sh[1][32 * s];
            ull a0[6] = {0,0,0,0,0,0}, a1[6] = {0,0,0,0,0,0};
            #pragma unroll
            for (int j = 0; j < 8; j++) {
                ulonglong2 hv0 = hp0[j];
                ulonglong2 hv1 = hp1[j];
                #pragma unroll
                for (int i = 0; i < 6; i++) {
                    a0[i] = fma2(w[i][j].x, hv0.x, a0[i]);
                    a0[i] = fma2(w[i][j].y, hv0.y, a0[i]);
                    a1[i] = fma2(w[i][j].x, hv1.x, a1[i]);
                    a1[i] = fma2(w[i][j].y, hv1.y, a1[i]);
                }
            }

            // export counterpart partials (packed f32x2)
            part_sh[p][0][s][0][l] = a0[eo + 0];
            part_sh[p][0][s][1][l] = a0[eo + 1];
            part_sh[p][0][s][2][l] = a0[eo + 2];
            part_sh[p][1][s][0][l] = a1[eo + 0];
            part_sh[p][1][s][1][l] = a1[eo + 1];
            part_sh[p][1][s][2][l] = a1[eo + 2];
            __syncthreads();

            // finalize own unit, row 0
            {
                float sr = hadd2(addf2(a0[ko + 0], part_sh[p][0][s ^ 1][0][l])) + bhr;
                float sz = hadd2(addf2(a0[ko + 1], part_sh[p][0][s ^ 1][1][l])) + bhz;
                float sn = hadd2(addf2(a0[ko + 2], part_sh[p][0][s ^ 1][2][l])) + bhn;
                float rr = siga(c00 + sr);
                float zz = siga(c01 + sz);
                float nn = tanha(c02 + rr * sn);
                hold0 = (1.f - zz) * nn + zz * hold0;
                h_sh[0][u] = hold0;
            }
            // finalize own unit, row 1
            {
                float sr = hadd2(addf2(a1[ko + 0], part_sh[p][1][s ^ 1][0][l])) + bhr;
                float sz = hadd2(addf2(a1[ko + 1], part_sh[p][1][s ^ 1][1][l])) + bhz;
                float sn = hadd2(addf2(a1[ko + 2], part_sh[p][1][s ^ 1][2][l])) + bhn;
                float rr = siga(c10 + sr);
                float zz = siga(c11 + sz);
                float nn = tanha(c12 + rr * sn);
                hold1 = (1.f - zz) * nn + zz * hold1;
                h_sh[1][u] = hold1;
            }
            __syncwarp();
            p ^= 1;
        }
    }
    __syncthreads();

    // ---- epilogue: backward GRU = ONE step from h=0 on x[:,T-1,:]; then fc ----
    #pragma unroll
    for (int r = 0; r < RR; r++) {
        const int j = tid;
        const int b = b0 + r;
        const float* xl = x + ((size_t)b * TT + (TT - 1)) * DD;
        float xv[DD];
        #pragma unroll
        for (int k = 0; k < DD; k++) xv[k] = __ldg(xl + k);

        float ar  = __ldg(b_ih_b + j)          + __ldg(b_hh_b + j);
        float az  = __ldg(b_ih_b + HH + j)     + __ldg(b_hh_b + HH + j);
        float anx = __ldg(b_ih_b + 2 * HH + j);
        float anh = __ldg(b_hh_b + 2 * HH + j);
        const float* wr = w_ih_b + (size_t)j * DD;
        const float* wz = w_ih_b + (size_t)(HH + j) * DD;
        const float* wn = w_ih_b + (size_t)(2 * HH + j) * DD;
        #pragma unroll
        for (int k = 0; k < DD; k++) {
            ar  += __ldg(wr + k) * xv[k];
            az  += __ldg(wz + k) * xv[k];
            anx += __ldg(wn + k) * xv[k];
        }
        float rb = siga(ar);
        float zb = siga(az);
        float nb = tanha(anx + rb * anh);
        float hb = (1.f - zb) * nb;            // h_prev = 0

        red_sh[r][j] = h_sh[r][j] * __ldg(fc_w + j) + hb * __ldg(fc_w + HH + j);
    }
    __syncthreads();
    if (tid < RR) {
        float sum = __ldg(fc_b);
        #pragma unroll
        for (int k = 0; k < HH; k++) sum += red_sh[tid][k];
        out[b0 + tid] = sum;
    }
}

extern "C" void kernel_launch(void* const* d_in, const int* in_sizes, int n_in,
                              void* d_out, int out_size)
{
    const float* x      = (const float*)d_in[0];
    const float* w_ih_f = (const float*)d_in[1];
    const float* w_hh_f = (const float*)d_in[2];
    const float* b_ih_f = (const float*)d_in[3];
    const float* b_hh_f = (const float*)d_in[4];
    const float* w_ih_b = (const float*)d_in[5];
    /* d_in[6] = w_hh_b unused: backward direction starts from h=0 */
    const float* b_ih_b = (const float*)d_in[7];
    const float* b_hh_b = (const float*)d_in[8];
    const float* fc_w   = (const float*)d_in[9];
    const float* fc_b   = (const float*)d_in[10];

    xg_kernel<<<dim3(TT / PT, BB), G3>>>(x, w_ih_f, b_ih_f);
    gru_rec_kernel<<<BB / RR, 64>>>(w_hh_f, b_hh_f, x,
                                    w_ih_b, b_ih_b, b_hh_b,
                                    fc_w, fc_b, (float*)d_out);
}

// round 6
// speedup vs baseline: 1.5741x; 1.5741x over previous
#include <cuda_runtime.h>
#include <cuda_fp16.h>

#define TT 512
#define BB 512
#define DD 16
#define HH 64
#define G3 192
#define PT 32          // timesteps per precompute CTA
#define BK 16          // timesteps per staged block in rec kernel
#define NBK (TT / BK)

typedef unsigned long long ull;

__device__ __forceinline__ ull fma2(ull a, ull b, ull c) {
    ull d;
    asm("fma.rn.f32x2 %0, %1, %2, %3;" : "=l"(d) : "l"(a), "l"(b), "l"(c));
    return d;
}
__device__ __forceinline__ float hadd2(ull a) {
    return __uint_as_float((unsigned)a) + __uint_as_float((unsigned)(a >> 32));
}
__device__ __forceinline__ float tanha(float x) {
    float y;
    asm("tanh.approx.f32 %0, %1;" : "=f"(y) : "f"(x));
    return y;
}
__device__ __forceinline__ float siga(float x) {
    return fmaf(0.5f, tanha(0.5f * x), 0.5f);
}
__device__ __forceinline__ void cpa16(unsigned smem, const void* gmem) {
    asm volatile("cp.async.ca.shared.global [%0], [%1], 16;\n"
                 :: "r"(smem), "l"(gmem));
}
__device__ __forceinline__ void cpa_commit() {
    asm volatile("cp.async.commit_group;\n" ::: "memory");
}
__device__ __forceinline__ void cpa_wait1() {
    asm volatile("cp.async.wait_group 1;\n" ::: "memory");
}

// scratch: xg[b][t][g] = x·w_ih^T + b_ih (+ b_hh for r,z gates), fp16
__device__ __half g_xg[(size_t)BB * TT * G3];

// ---------------------------------------------------------------------------
// Kernel 1: xg precompute. r,z gates (g<128) also get b_hh folded in.
// ---------------------------------------------------------------------------
__global__ __launch_bounds__(G3)
void xg_kernel(const float* __restrict__ x,
               const float* __restrict__ w_ih,
               const float* __restrict__ b_ih,
               const float* __restrict__ b_hh)
{
    __shared__ __align__(16) float xs[PT][DD];
    const int g  = threadIdx.x;
    const int b  = blockIdx.y;
    const int t0 = blockIdx.x * PT;

    ulonglong2 wv[DD / 4];
    {
        const ulonglong2* p = (const ulonglong2*)(w_ih + g * DD);
        #pragma unroll
        for (int j = 0; j < DD / 4; j++) wv[j] = p[j];
    }
    float bias = b_ih[g];
    if (g < 2 * HH) bias += b_hh[g];      // fold recurrent bias for r,z gates

    for (int i = g; i < PT * DD / 4; i += G3)
        ((float4*)&xs[0][0])[i] =
            ((const float4*)(x + ((size_t)b * TT + t0) * DD))[i];
    __syncthreads();

    #pragma unroll 8
    for (int tt = 0; tt < PT; tt++) {
        const ulonglong2* xp = (const ulonglong2*)xs[tt];
        ull a0 = 0ull, a1 = 0ull;
        #pragma unroll
        for (int j = 0; j < DD / 4; j++) {
            ulonglong2 xv = xp[j];
            a0 = fma2(wv[j].x, xv.x, a0);
            a1 = fma2(wv[j].y, xv.y, a1);
        }
        g_xg[((size_t)b * TT + t0 + tt) * G3 + g] =
            __float2half_rn(hadd2(a0) + hadd2(a1) + bias);
    }
}

// ---------------------------------------------------------------------------
// Kernel 2: forward recurrence. CTA = 64 threads = 1 row, grid 512.
// Thread `u` owns unit u completely: full 64-wide dots for its 3 gate rows
// (192 weight regs). No partial exchange; h double-buffered in SMEM; exactly
// ONE __syncthreads per step. xg staged via cp.async in 16-step fp16 blocks.
// ---------------------------------------------------------------------------
__global__ __launch_bounds__(64, 4)
void gru_rec_kernel(const float* __restrict__ w_hh,
                    const float* __restrict__ b_hh,
                    const float* __restrict__ x,
                    const float* __restrict__ w_ih_b,
                    const float* __restrict__ b_ih_b,
                    const float* __restrict__ b_hh_b,
                    const float* __restrict__ fc_w,
                    const float* __restrict__ fc_b,
                    float* __restrict__ out)
{
    __shared__ __align__(16) float h_sh[2][HH];
    __shared__ __align__(16) __half xg_sh[2][BK * G3];   // 6KB per buffer
    __shared__ float red_sh[HH];

    const int u = threadIdx.x;       // unit 0..63
    const int b = blockIdx.x;

    // full rows r(u), z(u), n(u) of w_hh: 3 x 64 floats = 48 ulonglong2
    ulonglong2 w[3][16];
    {
        const int rows[3] = { u, HH + u, 2 * HH + u };
        #pragma unroll
        for (int i = 0; i < 3; i++) {
            const ulonglong2* p = (const ulonglong2*)(w_hh + rows[i] * HH);
            #pragma unroll
            for (int j = 0; j < 16; j++) w[i][j] = p[j];
        }
    }
    const float bhn = b_hh[2 * HH + u];   // only n-gate bias stays separate

    const char* xg_g = (const char*)(g_xg + (size_t)b * TT * G3);
    const unsigned xg_sb = (unsigned)__cvta_generic_to_shared(&xg_sh[0][0]);
    // per block: BK*G3*2 = 6144 B = 384 x 16B chunks; 6 per thread

    float hold = 0.f;
    h_sh[0][u] = 0.f;

    // prologue: stage block 0 into buffer 0
    #pragma unroll
    for (int c = 0; c < 6; c++)
        cpa16(xg_sb + (u + 64 * c) * 16, xg_g + (u + 64 * c) * 16);
    cpa_commit();
    __syncthreads();

    int p = 0;
    for (int blk = 0; blk < NBK; ++blk) {
        if (blk + 1 < NBK) {
            unsigned dst = xg_sb + ((blk & 1) ? 0u : 6144u);
            const char* src = xg_g + (size_t)(blk + 1) * 6144;
            #pragma unroll
            for (int c = 0; c < 6; c++)
                cpa16(dst + (u + 64 * c) * 16, src + (u + 64 * c) * 16);
        }
        cpa_commit();
        cpa_wait1();
        __syncthreads();

        const __half* xb = &xg_sh[blk & 1][0];

        #pragma unroll 4
        for (int tt = 0; tt < BK; ++tt) {
            float cur0 = __half2float(xb[tt * G3 + u]);            // xr + br(total)
            float cur1 = __half2float(xb[tt * G3 + HH + u]);       // xz + bz(total)
            float cur2 = __half2float(xb[tt * G3 + 2 * HH + u]);   // xn + b_ih_n

            const ulonglong2* hp = (const ulonglong2*)&h_sh[p][0];
            ull a0 = 0ull, a1 = 0ull, a2 = 0ull;
            #pragma unroll
            for (int j = 0; j < 16; j++) {
                ulonglong2 hv = hp[j];
                a0 = fma2(w[0][j].x, hv.x, a0);
                a0 = fma2(w[0][j].y, hv.y, a0);
                a1 = fma2(w[1][j].x, hv.x, a1);
                a1 = fma2(w[1][j].y, hv.y, a1);
                a2 = fma2(w[2][j].x, hv.x, a2);
                a2 = fma2(w[2][j].y, hv.y, a2);
            }

            float rr = siga(cur0 + hadd2(a0));
            float zz = siga(cur1 + hadd2(a1));
            float nn = tanha(fmaf(rr, hadd2(a2) + bhn, cur2));
            hold = fmaf(zz, hold - nn, nn);     // (1-z)n + z h

            h_sh[p ^ 1][u] = hold;
            __syncthreads();
            p ^= 1;
        }
    }

    // ---- epilogue: backward GRU = ONE step from h=0 on x[:,T-1,:]; then fc ----
    {
        const int j = u;
        const float* xl = x + ((size_t)b * TT + (TT - 1)) * DD;
        float xv[DD];
        #pragma unroll
        for (int k = 0; k < DD; k++) xv[k] = __ldg(xl + k);

        float ar  = __ldg(b_ih_b + j)          + __ldg(b_hh_b + j);
        float az  = __ldg(b_ih_b + HH + j)     + __ldg(b_hh_b + HH + j);
        float anx = __ldg(b_ih_b + 2 * HH + j);
        float anh = __ldg(b_hh_b + 2 * HH + j);
        const float* wr = w_ih_b + (size_t)j * DD;
        const float* wz = w_ih_b + (size_t)(HH + j) * DD;
        const float* wn = w_ih_b + (size_t)(2 * HH + j) * DD;
        #pragma unroll
        for (int k = 0; k < DD; k++) {
            ar  += __ldg(wr + k) * xv[k];
            az  += __ldg(wz + k) * xv[k];
            anx += __ldg(wn + k) * xv[k];
        }
        float rb = siga(ar);
        float zb = siga(az);
        float nb = tanha(anx + rb * anh);
        float hb = (1.f - zb) * nb;            // h_prev = 0

        red_sh[j] = hold * __ldg(fc_w + j) + hb * __ldg(fc_w + HH + j);
    }
    __syncthreads();
    if (u == 0) {
        float sum = __ldg(fc_b);
        #pragma unroll
        for (int k = 0; k < HH; k++) sum += red_sh[k];
        out[b] = sum;
    }
}

extern "C" void kernel_launch(void* const* d_in, const int* in_sizes, int n_in,
                              void* d_out, int out_size)
{
    const float* x      = (const float*)d_in[0];
    const float* w_ih_f = (const float*)d_in[1];
    const float* w_hh_f = (const float*)d_in[2];
    const float* b_ih_f = (const float*)d_in[3];
    const float* b_hh_f = (const float*)d_in[4];
    const float* w_ih_b = (const float*)d_in[5];
    /* d_in[6] = w_hh_b unused: backward direction starts from h=0 */
    const float* b_ih_b = (const float*)d_in[7];
    const float* b_hh_b = (const float*)d_in[8];
    const float* fc_w   = (const float*)d_in[9];
    const float* fc_b   = (const float*)d_in[10];

    xg_kernel<<<dim3(TT / PT, BB), G3>>>(x, w_ih_f, b_ih_f, b_hh_f);
    gru_rec_kernel<<<BB, 64>>>(w_hh_f, b_hh_f, x,
                               w_ih_b, b_ih_b, b_hh_b,
                               fc_w, fc_b, (float*)d_out);
}